// round 1
// baseline (speedup 1.0000x reference)
#include <cuda_runtime.h>

#define BB 128
#define GG 20000
#define NELEM (BB * GG)        // 2,560,000
#define NPAIR (NELEM / 2)      // 1,280,000
#define HID 64
#define KB 9                   // NUM_BINS - 1
#define NSEG (HID + 1)         // 65 piecewise-linear segments

// Precomputed piecewise-linear representation of logits(x):
//   for x in segment s:  logit_k = A[s][k] * x + C[s][k]
__device__ float  g_T[HID];            // sorted breakpoints
__device__ float2 g_AC[NSEG * KB];     // .x = A, .y = C

// ---------------------------------------------------------------------------
// Precompute kernel: 1 block. Builds sorted breakpoints and per-segment
// (A, C) coefficients. 585 threads each own one (segment, bin) pair.
// ---------------------------------------------------------------------------
__global__ void precompute_kernel(const float* __restrict__ W1,
                                  const float* __restrict__ b1,
                                  const float* __restrict__ W2,
                                  const float* __restrict__ b2) {
    __shared__ float w1s[HID], b1s[HID], W2s[HID * KB], b2s[KB];
    __shared__ float t[HID], srt[HID];
    int tid = threadIdx.x;

    if (tid < HID)      { w1s[tid] = W1[tid]; b1s[tid] = b1[tid]; }
    if (tid < HID * KB) { W2s[tid] = W2[tid]; }
    if (tid < KB)       { b2s[tid] = b2[tid]; }
    __syncthreads();

    // breakpoints t_j = -b1_j / w1_j (clamped; w==0 -> sentinel, no crossing)
    if (tid < HID) {
        float w = w1s[tid], b = b1s[tid];
        float tv = (w != 0.0f) ? (-b / w) : 1e30f;
        if (!(tv > -1e30f)) tv = -1e30f;   // clamps and catches NaN
        if (tv > 1e30f)     tv = 1e30f;
        t[tid] = tv;
    }
    __syncthreads();

    // rank sort (64 elements, O(n) per thread, fully parallel)
    if (tid < HID) {
        float tv = t[tid];
        int rank = 0;
        #pragma unroll 8
        for (int i = 0; i < HID; i++) {
            float o = t[i];
            rank += (o < tv || (o == tv && i < tid)) ? 1 : 0;
        }
        srt[rank] = tv;
    }
    __syncthreads();

    if (tid < HID) g_T[tid] = srt[tid];

    // Per-(segment, bin) coefficient accumulation.
    if (tid < NSEG * KB) {
        int s = tid / KB;
        int k = tid - s * KB;
        float xm;
        if (s == 0)        xm = srt[0] - 1.0f;
        else if (s == HID) xm = srt[HID - 1] + 1.0f;
        else               xm = 0.5f * srt[s - 1] + 0.5f * srt[s];

        float A = 0.0f, C = b2s[k];
        #pragma unroll 4
        for (int j = 0; j < HID; j++) {
            float w = w1s[j], b = b1s[j];
            float h = fmaf(xm, w, b);
            float c = (h >= 0.0f) ? 1.0f : 0.01f;   // LeakyReLU slope, fixed in segment
            float wv = W2s[j * KB + k];
            A = fmaf(c * w, wv, A);
            C = fmaf(c * b, wv, C);
        }
        g_AC[tid] = make_float2(A, C);
    }
}

// ---------------------------------------------------------------------------
// Main kernel: one thread per element PAIR so the 10-float probs rows pack
// into 5 aligned float4 stores (80 bytes, 16B-aligned).
// ---------------------------------------------------------------------------
__device__ __forceinline__ void process_one(float x,
                                            const float* __restrict__ sT,
                                            const float2* __restrict__ sAC,
                                            float* o, float& mask) {
    if (x == 0.0f) {
        o[0] = 1.0f;
        #pragma unroll
        for (int k = 0; k < KB; k++) o[k + 1] = 0.0f;
        mask = 0.0f;
    } else {
        // branchless lower_bound over 64 sorted breakpoints: pos = #(T < x)
        int pos = 0;
        #pragma unroll
        for (int step = 32; step >= 1; step >>= 1)
            if (sT[pos + step - 1] < x) pos += step;

        const float2* ac = sAC + pos * KB;
        float lg[KB];
        float mx = -1e30f;
        #pragma unroll
        for (int k = 0; k < KB; k++) {
            float2 a = ac[k];
            lg[k] = fmaf(a.x, x, a.y);
            mx = fmaxf(mx, lg[k]);
        }
        float sum = 0.0f;
        #pragma unroll
        for (int k = 0; k < KB; k++) {
            float e = __expf(lg[k] - mx);
            lg[k] = e;
            sum += e;
        }
        float inv = __fdividef(1.0f, sum);
        o[0] = 0.0f;
        #pragma unroll
        for (int k = 0; k < KB; k++) o[k + 1] = lg[k] * inv;
        mask = 1.0f;
    }
}

__global__ void __launch_bounds__(256) expr_quant_kernel(const float* __restrict__ expr,
                                                         float* __restrict__ out) {
    __shared__ float  sT[HID];
    __shared__ float2 sAC[NSEG * KB];
    int tid = threadIdx.x;
    if (tid < HID) sT[tid] = g_T[tid];
    for (int i = tid; i < NSEG * KB; i += 256) sAC[i] = g_AC[i];
    __syncthreads();

    int pair = blockIdx.x * 256 + tid;
    if (pair >= NPAIR) return;

    float2 xv = *reinterpret_cast<const float2*>(expr + 2 * (size_t)pair);

    float o[20];
    float m0, m1;
    process_one(xv.x, sT, sAC, o,      m0);
    process_one(xv.y, sT, sAC, o + 10, m1);

    float4* dst = reinterpret_cast<float4*>(out + 20 * (size_t)pair);
    dst[0] = make_float4(o[0],  o[1],  o[2],  o[3]);
    dst[1] = make_float4(o[4],  o[5],  o[6],  o[7]);
    dst[2] = make_float4(o[8],  o[9],  o[10], o[11]);
    dst[3] = make_float4(o[12], o[13], o[14], o[15]);
    dst[4] = make_float4(o[16], o[17], o[18], o[19]);

    float2* mdst = reinterpret_cast<float2*>(out + (size_t)NELEM * 10 + 2 * (size_t)pair);
    *mdst = make_float2(m0, m1);
}

// ---------------------------------------------------------------------------
extern "C" void kernel_launch(void* const* d_in, const int* in_sizes, int n_in,
                              void* d_out, int out_size) {
    const float* expr = (const float*)d_in[0];
    const float* W1   = (const float*)d_in[1];
    const float* b1   = (const float*)d_in[2];
    const float* W2   = (const float*)d_in[3];
    const float* b2   = (const float*)d_in[4];
    float* out = (float*)d_out;

    precompute_kernel<<<1, 640>>>(W1, b1, W2, b2);
    expr_quant_kernel<<<(NPAIR + 255) / 256, 256>>>(expr, out);
}